// round 8
// baseline (speedup 1.0000x reference)
#include <cuda_runtime.h>

// Shapes: x [8,16,4,8192,2] f32; psi_hat [24,16384,2]; phi_hat [1,16384,2];
// idx [32,2] int32 (sniffed, tolerates int64); out [8,32,4,8192,2] f32.
#define N_FFT    16384
#define MASK     (N_FFT - 1)
#define T_LEN    8192
#define NT       1024
#define NSEQ     512
// Bank-conflict-avoiding padded smem index: one extra float2 per 16.
#define P(i) ((i) + ((i) >> 4))
#define SMEM_F2    (N_FFT + N_FFT / 16)
#define SMEM_BYTES (SMEM_F2 * 8)             // 139264 bytes

__device__ __align__(16) float2 g_twN[N_FFT];            // full twiddle table, 128KB
__device__ __align__(16) float2 g_xhat[NSEQ * N_FFT];    // 64 MiB
__device__ __align__(16) float2 g_filtrev[26 * N_FFT];   // digit-reversed filters
__device__ int g_idx[64];

__device__ __forceinline__ float2 cmul(float2 a, float2 b) {
    return make_float2(fmaf(a.x, b.x, -a.y * b.y), fmaf(a.x, b.y, a.y * b.x));
}

// Twiddle triples: forward indices satisfy 3j < N (max j = 4095).
__device__ __forceinline__ void tw3_fwd(int j, float2& w1, float2& w2, float2& w3) {
    w1 = g_twN[j]; w2 = g_twN[2 * j]; w3 = g_twN[3 * j];
}
// Inverse: conj(W^j) = W^{-j mod N} via index negation (exact).
__device__ __forceinline__ void tw3_inv(int j, float2& w1, float2& w2, float2& w3) {
    w1 = g_twN[(-j) & MASK]; w2 = g_twN[(-2 * j) & MASK]; w3 = g_twN[(-3 * j) & MASK];
}

// Forward (DIF) radix-4 butterfly with preloaded twiddles (applied to outputs).
__device__ __forceinline__ void bfly4_dif_t(float2& x0, float2& x1, float2& x2,
                                            float2& x3, float2 w1, float2 w2, float2 w3) {
    float2 t0 = make_float2(x0.x + x2.x, x0.y + x2.y);
    float2 t1 = make_float2(x0.x - x2.x, x0.y - x2.y);
    float2 t2 = make_float2(x1.x + x3.x, x1.y + x3.y);
    float2 t3 = make_float2(x1.x - x3.x, x1.y - x3.y);
    x0 = make_float2(t0.x + t2.x, t0.y + t2.y);
    float2 y1 = make_float2(t1.x + t3.y, t1.y - t3.x);   // t1 - i*t3
    float2 y2 = make_float2(t0.x - t2.x, t0.y - t2.y);
    float2 y3 = make_float2(t1.x - t3.y, t1.y + t3.x);   // t1 + i*t3
    x1 = cmul(y1, w1);
    x2 = cmul(y2, w2);
    x3 = cmul(y3, w3);
}

__device__ __forceinline__ void bfly4_dif_nw(float2& x0, float2& x1,
                                             float2& x2, float2& x3) {
    float2 t0 = make_float2(x0.x + x2.x, x0.y + x2.y);
    float2 t1 = make_float2(x0.x - x2.x, x0.y - x2.y);
    float2 t2 = make_float2(x1.x + x3.x, x1.y + x3.y);
    float2 t3 = make_float2(x1.x - x3.x, x1.y - x3.y);
    x0 = make_float2(t0.x + t2.x, t0.y + t2.y);
    x1 = make_float2(t1.x + t3.y, t1.y - t3.x);
    x2 = make_float2(t0.x - t2.x, t0.y - t2.y);
    x3 = make_float2(t1.x - t3.y, t1.y + t3.x);
}

// Inverse (DIT) radix-4 with preloaded conjugated twiddles (applied to inputs).
__device__ __forceinline__ void bfly4_dit_t(float2& x0, float2& x1, float2& x2,
                                            float2& x3, float2 w1, float2 w2, float2 w3) {
    float2 b1 = cmul(x1, w1);
    float2 b2 = cmul(x2, w2);
    float2 b3 = cmul(x3, w3);
    float2 t0 = make_float2(x0.x + b2.x, x0.y + b2.y);
    float2 t1 = make_float2(x0.x - b2.x, x0.y - b2.y);
    float2 t2 = make_float2(b1.x + b3.x, b1.y + b3.y);
    float2 t3 = make_float2(b1.x - b3.x, b1.y - b3.y);
    x0 = make_float2(t0.x + t2.x, t0.y + t2.y);
    x1 = make_float2(t1.x - t3.y, t1.y + t3.x);          // t1 + i*t3
    x2 = make_float2(t0.x - t2.x, t0.y - t2.y);
    x3 = make_float2(t1.x + t3.y, t1.y - t3.x);          // t1 - i*t3
}

__device__ __forceinline__ void bfly4_dit_nw(float2& x0, float2& x1,
                                             float2& x2, float2& x3) {
    float2 t0 = make_float2(x0.x + x2.x, x0.y + x2.y);
    float2 t1 = make_float2(x0.x - x2.x, x0.y - x2.y);
    float2 t2 = make_float2(x1.x + x3.x, x1.y + x3.y);
    float2 t3 = make_float2(x1.x - x3.x, x1.y - x3.y);
    x0 = make_float2(t0.x + t2.x, t0.y + t2.y);
    x1 = make_float2(t1.x - t3.y, t1.y + t3.x);
    x2 = make_float2(t0.x - t2.x, t0.y - t2.y);
    x3 = make_float2(t1.x + t3.y, t1.y - t3.x);
}

// Fused DIF stage pair (S, S+1), one 16-point unit per thread, smem->smem.
template <int S>
__device__ __forceinline__ void fwd_fused_phase(float2* sm, int v) {
    constexpr int l2 = 12 - 2 * S;
    constexpr int L  = 1 << l2;
    constexpr int L4 = L >> 2;
    int block = v >> (l2 - 2);
    int j0 = v & (L4 - 1);
    int base = (block << (l2 + 2)) + j0;
    float2 d[4][4];
#pragma unroll
    for (int m = 0; m < 4; m++)
#pragma unroll
        for (int q = 0; q < 4; q++)
            d[m][q] = sm[P(base + m * L4 + q * L)];
#pragma unroll
    for (int m = 0; m < 4; m++) {
        float2 w1, w2, w3;
        tw3_fwd((j0 + m * L4) << (2 * S), w1, w2, w3);
        bfly4_dif_t(d[m][0], d[m][1], d[m][2], d[m][3], w1, w2, w3);
    }
    {
        float2 w1, w2, w3;
        tw3_fwd(j0 << (2 * S + 2), w1, w2, w3);
#pragma unroll
        for (int q = 0; q < 4; q++)
            bfly4_dif_t(d[0][q], d[1][q], d[2][q], d[3][q], w1, w2, w3);
    }
#pragma unroll
    for (int m = 0; m < 4; m++)
#pragma unroll
        for (int q = 0; q < 4; q++)
            sm[P(base + m * L4 + q * L)] = d[m][q];
    __syncthreads();
}

// Exact inverse: stage S+1 then S, conjugated twiddles.
template <int S>
__device__ __forceinline__ void inv_fused_phase(float2* sm, int v) {
    constexpr int l2 = 12 - 2 * S;
    constexpr int L  = 1 << l2;
    constexpr int L4 = L >> 2;
    int block = v >> (l2 - 2);
    int j0 = v & (L4 - 1);
    int base = (block << (l2 + 2)) + j0;
    float2 d[4][4];
#pragma unroll
    for (int m = 0; m < 4; m++)
#pragma unroll
        for (int q = 0; q < 4; q++)
            d[m][q] = sm[P(base + m * L4 + q * L)];
    {
        float2 w1, w2, w3;
        tw3_inv(j0 << (2 * S + 2), w1, w2, w3);
#pragma unroll
        for (int q = 0; q < 4; q++)
            bfly4_dit_t(d[0][q], d[1][q], d[2][q], d[3][q], w1, w2, w3);
    }
#pragma unroll
    for (int m = 0; m < 4; m++) {
        float2 w1, w2, w3;
        tw3_inv((j0 + m * L4) << (2 * S), w1, w2, w3);
        bfly4_dit_t(d[m][0], d[m][1], d[m][2], d[m][3], w1, w2, w3);
    }
#pragma unroll
    for (int m = 0; m < 4; m++)
#pragma unroll
        for (int q = 0; q < 4; q++)
            sm[P(base + m * L4 + q * L)] = d[m][q];
    __syncthreads();
}

__device__ __forceinline__ int digitrev4(int v) {
    int r = 0;
#pragma unroll
    for (int i = 0; i < 7; i++) { r = (r << 2) | (v & 3); v >>= 2; }
    return r;
}

__global__ void tw_init_kernel() {
    int k = blockIdx.x * blockDim.x + threadIdx.x;
    if (k < N_FFT) {
        double s, c;
        sincospi(-2.0 * (double)k / (double)N_FFT, &s, &c);
        g_twN[k] = make_float2((float)c, (float)s);
    }
}

// Normalize idx regardless of int32/int64 storage (layout sniff, see R2-R4).
__global__ void idx_norm_kernel(const int* __restrict__ raw) {
    __shared__ int nz;
    int tid = threadIdx.x;
    if (tid == 0) nz = 0;
    __syncthreads();
    if (tid < 32 && raw[2 * tid + 1] != 0) atomicOr(&nz, 1);
    __syncthreads();
    if (tid < 64) {
        int v = nz ? raw[tid] : raw[2 * tid];
        g_idx[tid] = min(max(v, 0), (tid & 1) ? 25 : 15);
    }
}

// Pre-permute 26 filter spectra (24 psi + phi + phi) into digit-reversed order.
__global__ void filt_prep_kernel(const float* __restrict__ psi,
                                 const float* __restrict__ phi) {
    int p = blockIdx.x * blockDim.x + threadIdx.x;
    int row = p >> 14;
    if (row >= 26) return;
    int q = p & (N_FFT - 1);
    int src = digitrev4(q);
    const float* f = (row < 24) ? (psi + (size_t)row * N_FFT * 2) : phi;
    g_filtrev[p] = make_float2(f[2 * src], f[2 * src + 1]);
}

// Forward: [gmem reflect-read + stages 0,1] -> phase<2> -> phase<4> ->
// [stage 6 + gmem store]. Natural in -> digit-reversed out.
__global__ void __launch_bounds__(NT)
fwd_fft_kernel(const float* __restrict__ x) {
    extern __shared__ float2 sm[];
    const int seq = blockIdx.x;
    const float2* xi = (const float2*)(x + (size_t)seq * T_LEN * 2);
    const int tid = threadIdx.x;
    {
        const int v = tid;
        float2 d[4][4];
#pragma unroll
        for (int m = 0; m < 4; m++) {
            int g0 = v + m * 1024;
            d[m][0] = xi[g0];
            d[m][1] = xi[g0 + 4096];
            d[m][2] = xi[8191 - g0];       // reflected half
            d[m][3] = xi[4095 - g0];
        }
#pragma unroll
        for (int m = 0; m < 4; m++) {
            float2 w1, w2, w3;
            tw3_fwd(v + m * 1024, w1, w2, w3);
            bfly4_dif_t(d[m][0], d[m][1], d[m][2], d[m][3], w1, w2, w3);
        }
        {
            float2 w1, w2, w3;
            tw3_fwd(v << 2, w1, w2, w3);
#pragma unroll
            for (int q = 0; q < 4; q++)
                bfly4_dif_t(d[0][q], d[1][q], d[2][q], d[3][q], w1, w2, w3);
        }
#pragma unroll
        for (int m = 0; m < 4; m++)
#pragma unroll
            for (int q = 0; q < 4; q++)
                sm[P(v + m * 1024 + q * 4096)] = d[m][q];
    }
    __syncthreads();

    fwd_fused_phase<2>(sm, tid);
    fwd_fused_phase<4>(sm, tid);

    float4* out4 = (float4*)(g_xhat + (size_t)seq * N_FFT);
#pragma unroll
    for (int k = 0; k < 4; k++) {
        int base = 4 * (tid + k * NT);
        float2 a0 = sm[P(base)],     a1 = sm[P(base + 1)];
        float2 a2 = sm[P(base + 2)], a3 = sm[P(base + 3)];
        bfly4_dif_nw(a0, a1, a2, a3);
        out4[base >> 1]       = make_float4(a0.x, a0.y, a1.x, a1.y);
        out4[(base >> 1) + 1] = make_float4(a2.x, a2.y, a3.x, a3.y);
    }
}

// Inverse: [gmem gather*filter + stage 6] -> phase<4> -> phase<2> ->
// phase<0> -> scaled store of first T samples.
__global__ void __launch_bounds__(NT)
inv_fft_kernel(float* __restrict__ out) {
    extern __shared__ float2 sm[];
    const int b  = blockIdx.x;
    const int a  = b & 3;
    const int cj = (b >> 2) & 31;
    const int c  = b >> 7;
    const int jr = g_idx[2 * cj];
    const int f  = g_idx[2 * cj + 1];
    const int src = (c * 16 + jr) * 4 + a;
    const int tid = threadIdx.x;

    const float4* xh4 = (const float4*)(g_xhat + (size_t)src * N_FFT);
    const float4* fr4 = (const float4*)(g_filtrev + (size_t)f * N_FFT);
#pragma unroll
    for (int k = 0; k < 4; k++) {
        int base = 4 * (tid + k * NT);
        float4 xa = xh4[base >> 1], xb = xh4[(base >> 1) + 1];
        float4 fa = fr4[base >> 1], fb = fr4[(base >> 1) + 1];
        float2 a0 = cmul(make_float2(xa.x, xa.y), make_float2(fa.x, fa.y));
        float2 a1 = cmul(make_float2(xa.z, xa.w), make_float2(fa.z, fa.w));
        float2 a2 = cmul(make_float2(xb.x, xb.y), make_float2(fb.x, fb.y));
        float2 a3 = cmul(make_float2(xb.z, xb.w), make_float2(fb.z, fb.w));
        bfly4_dit_nw(a0, a1, a2, a3);
        sm[P(base)] = a0;     sm[P(base + 1)] = a1;
        sm[P(base + 2)] = a2; sm[P(base + 3)] = a3;
    }
    __syncthreads();

    inv_fused_phase<4>(sm, tid);
    inv_fused_phase<2>(sm, tid);
    inv_fused_phase<0>(sm, tid);

    float2* o = (float2*)(out + (size_t)b * T_LEN * 2);
    const float scale = 1.0f / (float)N_FFT;
#pragma unroll
    for (int k = 0; k < T_LEN / NT; k++) {
        int t = tid + k * NT;
        float2 v = sm[P(t)];
        o[t] = make_float2(v.x * scale, v.y * scale);
    }
}

extern "C" void kernel_launch(void* const* d_in, const int* in_sizes, int n_in,
                              void* d_out, int out_size) {
    const float* x   = (const float*)d_in[0];
    const float* psi = (const float*)d_in[1];
    const float* phi = (const float*)d_in[2];
    const int* idxr  = (const int*)d_in[3];
    float* out       = (float*)d_out;

    cudaFuncSetAttribute(fwd_fft_kernel,
                         cudaFuncAttributeMaxDynamicSharedMemorySize, SMEM_BYTES);
    cudaFuncSetAttribute(inv_fft_kernel,
                         cudaFuncAttributeMaxDynamicSharedMemorySize, SMEM_BYTES);

    tw_init_kernel<<<(N_FFT + 511) / 512, 512>>>();
    idx_norm_kernel<<<1, 64>>>(idxr);
    filt_prep_kernel<<<(26 * N_FFT + 511) / 512, 512>>>(psi, phi);
    fwd_fft_kernel<<<NSEQ, NT, SMEM_BYTES>>>(x);
    inv_fft_kernel<<<1024, NT, SMEM_BYTES>>>(out);
}

// round 10
// speedup vs baseline: 1.2716x; 1.2716x over previous
#include <cuda_runtime.h>

// Shapes: x [8,16,4,8192,2] f32; psi_hat [24,16384,2]; phi_hat [1,16384,2];
// idx [32,2] int32 (sniffed, tolerates int64); out [8,32,4,8192,2] f32.
#define N_FFT    16384
#define T_LEN    8192
#define NT       1024
#define NSEQ     512
// Bank-conflict-avoiding padded smem index: one extra float2 per 16.
#define P(i) ((i) + ((i) >> 4))
#define SMEM_F2    (N_FFT + N_FFT / 16)
#define SMEM_BYTES (SMEM_F2 * 8)             // 139264 bytes

__device__ __align__(16) float2 g_tw[N_FFT / 4];         // 32KB, L1-hot
__device__ __align__(16) float2 g_xhat[NSEQ * N_FFT];    // 64 MiB
__device__ __align__(16) float2 g_filtrev[26 * N_FFT];   // digit-reversed filters
__device__ int g_idx[64];        // normalized (jr, f) pairs
__device__ int g_cnt[16];        // #cj per jr
__device__ int g_list[512];      // g_list[jr*32 + i] = cj
__device__ int g_sched[NSEQ];    // CTA schedule: heavy jr first

__device__ __forceinline__ float2 cmul(float2 a, float2 b) {
    return make_float2(fmaf(a.x, b.x, -a.y * b.y), fmaf(a.x, b.y, a.y * b.x));
}

// DIF butterfly with all three twiddles given (applied to outputs).
__device__ __forceinline__ void bfly4_dif_t(float2& x0, float2& x1, float2& x2,
                                            float2& x3, float2 w1, float2 w2, float2 w3) {
    float2 t0 = make_float2(x0.x + x2.x, x0.y + x2.y);
    float2 t1 = make_float2(x0.x - x2.x, x0.y - x2.y);
    float2 t2 = make_float2(x1.x + x3.x, x1.y + x3.y);
    float2 t3 = make_float2(x1.x - x3.x, x1.y - x3.y);
    x0 = make_float2(t0.x + t2.x, t0.y + t2.y);
    float2 y1 = make_float2(t1.x + t3.y, t1.y - t3.x);   // t1 - i*t3
    float2 y2 = make_float2(t0.x - t2.x, t0.y - t2.y);
    float2 y3 = make_float2(t1.x - t3.y, t1.y + t3.x);   // t1 + i*t3
    x1 = cmul(y1, w1);
    x2 = cmul(y2, w2);
    x3 = cmul(y3, w3);
}
// DIF with w2,w3 derived from w1 (FMA pipe has spare capacity; keep loads off L1).
__device__ __forceinline__ void bfly4_dif(float2& x0, float2& x1, float2& x2,
                                          float2& x3, float2 w1) {
    float2 w2 = cmul(w1, w1);
    bfly4_dif_t(x0, x1, x2, x3, w1, w2, cmul(w2, w1));
}

__device__ __forceinline__ void bfly4_dif_nw(float2& x0, float2& x1,
                                             float2& x2, float2& x3) {
    float2 t0 = make_float2(x0.x + x2.x, x0.y + x2.y);
    float2 t1 = make_float2(x0.x - x2.x, x0.y - x2.y);
    float2 t2 = make_float2(x1.x + x3.x, x1.y + x3.y);
    float2 t3 = make_float2(x1.x - x3.x, x1.y - x3.y);
    x0 = make_float2(t0.x + t2.x, t0.y + t2.y);
    x1 = make_float2(t1.x + t3.y, t1.y - t3.x);
    x2 = make_float2(t0.x - t2.x, t0.y - t2.y);
    x3 = make_float2(t1.x - t3.y, t1.y + t3.x);
}

// DIT butterfly, conjugated twiddles given (applied to inputs).
__device__ __forceinline__ void bfly4_dit_t(float2& x0, float2& x1, float2& x2,
                                            float2& x3, float2 w1, float2 w2, float2 w3) {
    float2 b1 = cmul(x1, w1);
    float2 b2 = cmul(x2, w2);
    float2 b3 = cmul(x3, w3);
    float2 t0 = make_float2(x0.x + b2.x, x0.y + b2.y);
    float2 t1 = make_float2(x0.x - b2.x, x0.y - b2.y);
    float2 t2 = make_float2(b1.x + b3.x, b1.y + b3.y);
    float2 t3 = make_float2(b1.x - b3.x, b1.y - b3.y);
    x0 = make_float2(t0.x + t2.x, t0.y + t2.y);
    x1 = make_float2(t1.x - t3.y, t1.y + t3.x);          // t1 + i*t3
    x2 = make_float2(t0.x - t2.x, t0.y - t2.y);
    x3 = make_float2(t1.x + t3.y, t1.y - t3.x);          // t1 - i*t3
}
__device__ __forceinline__ void bfly4_dit(float2& x0, float2& x1, float2& x2,
                                          float2& x3, float2 w1c) {
    float2 w2 = cmul(w1c, w1c);
    bfly4_dit_t(x0, x1, x2, x3, w1c, w2, cmul(w2, w1c));
}

__device__ __forceinline__ void bfly4_dit_nw(float2& x0, float2& x1,
                                             float2& x2, float2& x3) {
    float2 t0 = make_float2(x0.x + x2.x, x0.y + x2.y);
    float2 t1 = make_float2(x0.x - x2.x, x0.y - x2.y);
    float2 t2 = make_float2(x1.x + x3.x, x1.y + x3.y);
    float2 t3 = make_float2(x1.x - x3.x, x1.y - x3.y);
    x0 = make_float2(t0.x + t2.x, t0.y + t2.y);
    x1 = make_float2(t1.x - t3.y, t1.y + t3.x);
    x2 = make_float2(t0.x - t2.x, t0.y - t2.y);
    x3 = make_float2(t1.x + t3.y, t1.y - t3.x);
}

// Fused DIF stage pair (S, S+1), one 16-point unit per thread, smem->smem.
template <int S>
__device__ __forceinline__ void fwd_fused_phase(float2* sm, int v) {
    constexpr int l2 = 12 - 2 * S;
    constexpr int L  = 1 << l2;
    constexpr int L4 = L >> 2;
    int block = v >> (l2 - 2);
    int j0 = v & (L4 - 1);
    int base = (block << (l2 + 2)) + j0;
    float2 d[4][4];
#pragma unroll
    for (int m = 0; m < 4; m++)
#pragma unroll
        for (int q = 0; q < 4; q++)
            d[m][q] = sm[P(base + m * L4 + q * L)];
#pragma unroll
    for (int m = 0; m < 4; m++)
        bfly4_dif(d[m][0], d[m][1], d[m][2], d[m][3],
                  g_tw[(j0 + m * L4) << (2 * S)]);
    {
        float2 w1 = g_tw[j0 << (2 * S + 2)];
        float2 w2 = cmul(w1, w1);
        float2 w3 = cmul(w2, w1);
#pragma unroll
        for (int q = 0; q < 4; q++)
            bfly4_dif_t(d[0][q], d[1][q], d[2][q], d[3][q], w1, w2, w3);
    }
#pragma unroll
    for (int m = 0; m < 4; m++)
#pragma unroll
        for (int q = 0; q < 4; q++)
            sm[P(base + m * L4 + q * L)] = d[m][q];
    __syncthreads();
}

// Exact inverse: stage S+1 then S, conjugated twiddles.
template <int S>
__device__ __forceinline__ void inv_fused_phase(float2* sm, int v) {
    constexpr int l2 = 12 - 2 * S;
    constexpr int L  = 1 << l2;
    constexpr int L4 = L >> 2;
    int block = v >> (l2 - 2);
    int j0 = v & (L4 - 1);
    int base = (block << (l2 + 2)) + j0;
    float2 d[4][4];
#pragma unroll
    for (int m = 0; m < 4; m++)
#pragma unroll
        for (int q = 0; q < 4; q++)
            d[m][q] = sm[P(base + m * L4 + q * L)];
    {
        float2 w1 = g_tw[j0 << (2 * S + 2)];
        w1.y = -w1.y;
        float2 w2 = cmul(w1, w1);
        float2 w3 = cmul(w2, w1);
#pragma unroll
        for (int q = 0; q < 4; q++)
            bfly4_dit_t(d[0][q], d[1][q], d[2][q], d[3][q], w1, w2, w3);
    }
#pragma unroll
    for (int m = 0; m < 4; m++) {
        float2 w1 = g_tw[(j0 + m * L4) << (2 * S)];
        w1.y = -w1.y;
        bfly4_dit(d[m][0], d[m][1], d[m][2], d[m][3], w1);
    }
#pragma unroll
    for (int m = 0; m < 4; m++)
#pragma unroll
        for (int q = 0; q < 4; q++)
            sm[P(base + m * L4 + q * L)] = d[m][q];
    __syncthreads();
}

__device__ __forceinline__ int digitrev4(int v) {
    int r = 0;
#pragma unroll
    for (int i = 0; i < 7; i++) { r = (r << 2) | (v & 3); v >>= 2; }
    return r;
}

__global__ void tw_init_kernel() {
    int k = blockIdx.x * blockDim.x + threadIdx.x;
    if (k < N_FFT / 4) {
        double s, c;
        sincospi(-2.0 * (double)k / (double)N_FFT, &s, &c);
        g_tw[k] = make_float2((float)c, (float)s);
    }
}

// Normalize idx (int32/int64 sniff, see R2-R4) + build per-jr cj lists and a
// CTA schedule ordered by descending per-jr load (heaviest CTAs dispatch first).
__global__ void idx_norm_kernel(const int* __restrict__ raw) {
    __shared__ int nz;
    int tid = threadIdx.x;
    if (tid == 0) nz = 0;
    __syncthreads();
    if (tid < 32 && raw[2 * tid + 1] != 0) atomicOr(&nz, 1);
    __syncthreads();
    if (tid < 64) {
        int v = nz ? raw[tid] : raw[2 * tid];
        g_idx[tid] = min(max(v, 0), (tid & 1) ? 25 : 15);
    }
    __syncthreads();
    if (tid == 0) {
        int cnt[16];
        for (int j = 0; j < 16; j++) cnt[j] = 0;
        for (int cj = 0; cj < 32; cj++) {
            int jr = g_idx[2 * cj];
            g_list[jr * 32 + cnt[jr]] = cj;
            cnt[jr]++;
        }
        for (int j = 0; j < 16; j++) g_cnt[j] = cnt[j];
        // order jr by cnt desc (selection sort over 16)
        int ord[16];
        for (int j = 0; j < 16; j++) ord[j] = j;
        for (int i = 0; i < 16; i++) {
            int best = i;
            for (int j = i + 1; j < 16; j++)
                if (cnt[ord[j]] > cnt[ord[best]]) best = j;
            int t = ord[i]; ord[i] = ord[best]; ord[best] = t;
        }
        int p = 0;
        for (int i = 0; i < 16; i++)
            for (int ca = 0; ca < 32; ca++)       // ca = c*4 + a
                g_sched[p++] = (ord[i] << 5) | ca;
    }
}

// Pre-permute 26 filter spectra (24 psi + phi + phi) into digit-reversed order.
__global__ void filt_prep_kernel(const float* __restrict__ psi,
                                 const float* __restrict__ phi) {
    int p = blockIdx.x * blockDim.x + threadIdx.x;
    int row = p >> 14;
    if (row >= 26) return;
    int q = p & (N_FFT - 1);
    int src = digitrev4(q);
    const float* f = (row < 24) ? (psi + (size_t)row * N_FFT * 2) : phi;
    g_filtrev[p] = make_float2(f[2 * src], f[2 * src + 1]);
}

// Fused kernel: each CTA computes the forward FFT for its (c,jr,a) sequence,
// then all inverse rows consuming that spectrum. No inter-CTA sync anywhere.
__global__ void __launch_bounds__(NT)
conv_kernel(const float* __restrict__ x, float* __restrict__ out) {
    extern __shared__ float2 sm[];
    const int s   = g_sched[blockIdx.x];
    const int jr  = s >> 5;
    const int c   = (s >> 2) & 7;
    const int a   = s & 3;
    const int cnt = g_cnt[jr];
    if (cnt == 0) return;                       // spectrum never used
    const int seq = (c * 16 + jr) * 4 + a;
    const int tid = threadIdx.x;

    // ---- forward: [gmem reflect-read + stages 0,1] -> ph<2> -> ph<4> ->
    //      [stage 6 + store to private g_xhat slice] ----
    {
        const float2* xi = (const float2*)(x + (size_t)seq * T_LEN * 2);
        const int v = tid;
        float2 d[4][4];
#pragma unroll
        for (int m = 0; m < 4; m++) {
            int g0 = v + m * 1024;
            d[m][0] = xi[g0];
            d[m][1] = xi[g0 + 4096];
            d[m][2] = xi[8191 - g0];            // reflected half
            d[m][3] = xi[4095 - g0];
        }
#pragma unroll
        for (int m = 0; m < 4; m++)
            bfly4_dif(d[m][0], d[m][1], d[m][2], d[m][3], g_tw[v + m * 1024]);
        {
            float2 w1 = g_tw[v << 2];
            float2 w2 = cmul(w1, w1);
            float2 w3 = cmul(w2, w1);
#pragma unroll
            for (int q = 0; q < 4; q++)
                bfly4_dif_t(d[0][q], d[1][q], d[2][q], d[3][q], w1, w2, w3);
        }
#pragma unroll
        for (int m = 0; m < 4; m++)
#pragma unroll
            for (int q = 0; q < 4; q++)
                sm[P(v + m * 1024 + q * 4096)] = d[m][q];
    }
    __syncthreads();

    fwd_fused_phase<2>(sm, tid);
    fwd_fused_phase<4>(sm, tid);

    float4* xout4 = (float4*)(g_xhat + (size_t)seq * N_FFT);
#pragma unroll
    for (int k = 0; k < 4; k++) {
        int base = 4 * (tid + k * NT);
        float2 a0 = sm[P(base)],     a1 = sm[P(base + 1)];
        float2 a2 = sm[P(base + 2)], a3 = sm[P(base + 3)];
        bfly4_dif_nw(a0, a1, a2, a3);
        xout4[base >> 1]       = make_float4(a0.x, a0.y, a1.x, a1.y);
        xout4[(base >> 1) + 1] = make_float4(a2.x, a2.y, a3.x, a3.y);
    }
    // note: each thread re-reads exactly the addresses it wrote (same-thread
    // program order) in the inverse start below — no fence needed.

    const float4* xh4 = (const float4*)(g_xhat + (size_t)seq * N_FFT);

    // ---- inverse rows sharing this spectrum ----
    for (int i = 0; i < cnt; i++) {
        const int cj = g_list[jr * 32 + i];
        const int f  = g_idx[2 * cj + 1];
        const float4* fr4 = (const float4*)(g_filtrev + (size_t)f * N_FFT);

        __syncthreads();                        // prior smem reads complete
#pragma unroll
        for (int k = 0; k < 4; k++) {
            int base = 4 * (tid + k * NT);
            float4 xa = xh4[base >> 1], xb = xh4[(base >> 1) + 1];
            float4 fa = fr4[base >> 1], fb = fr4[(base >> 1) + 1];
            float2 a0 = cmul(make_float2(xa.x, xa.y), make_float2(fa.x, fa.y));
            float2 a1 = cmul(make_float2(xa.z, xa.w), make_float2(fa.z, fa.w));
            float2 a2 = cmul(make_float2(xb.x, xb.y), make_float2(fb.x, fb.y));
            float2 a3 = cmul(make_float2(xb.z, xb.w), make_float2(fb.z, fb.w));
            bfly4_dit_nw(a0, a1, a2, a3);
            sm[P(base)] = a0;     sm[P(base + 1)] = a1;
            sm[P(base + 2)] = a2; sm[P(base + 3)] = a3;
        }
        __syncthreads();

        inv_fused_phase<4>(sm, tid);
        inv_fused_phase<2>(sm, tid);
        inv_fused_phase<0>(sm, tid);

        float2* o = (float2*)(out + (size_t)((c * 32 + cj) * 4 + a) * T_LEN * 2);
        const float scale = 1.0f / (float)N_FFT;
#pragma unroll
        for (int k = 0; k < T_LEN / NT; k++) {
            int t = tid + k * NT;
            float2 v = sm[P(t)];
            o[t] = make_float2(v.x * scale, v.y * scale);
        }
    }
}

extern "C" void kernel_launch(void* const* d_in, const int* in_sizes, int n_in,
                              void* d_out, int out_size) {
    const float* x   = (const float*)d_in[0];
    const float* psi = (const float*)d_in[1];
    const float* phi = (const float*)d_in[2];
    const int* idxr  = (const int*)d_in[3];
    float* out       = (float*)d_out;

    cudaFuncSetAttribute(conv_kernel,
                         cudaFuncAttributeMaxDynamicSharedMemorySize, SMEM_BYTES);

    tw_init_kernel<<<(N_FFT / 4 + 511) / 512, 512>>>();
    idx_norm_kernel<<<1, 64>>>(idxr);
    filt_prep_kernel<<<(26 * N_FFT + 511) / 512, 512>>>(psi, phi);
    conv_kernel<<<NSEQ, NT, SMEM_BYTES>>>(x, out);
}

// round 11
// speedup vs baseline: 1.5174x; 1.1934x over previous
#include <cuda_runtime.h>

// Shapes: x [8,16,4,8192,2] f32; psi_hat [24,16384,2]; phi_hat [1,16384,2];
// idx [32,2] int32 (sniffed, tolerates int64); out [8,32,4,8192,2] f32.
#define N_FFT    16384
#define T_LEN    8192
#define NT       1024
#define NSEQ     512
// Bank-conflict-avoiding padded smem index: one extra float2 per 16.
#define P(i) ((i) + ((i) >> 4))
#define SMEM_F2    (N_FFT + N_FFT / 16)
#define SMEM_BYTES (SMEM_F2 * 8)             // 139264 bytes

__device__ __align__(16) float2 g_tw[N_FFT / 4];         // 32KB, L1-hot
__device__ __align__(16) float2 g_xhat[NSEQ * N_FFT];    // 64 MiB
__device__ __align__(16) float2 g_filtrev[26 * N_FFT];   // digit-reversed filters
__device__ int g_idx[64];        // normalized (jr, f) pairs
__device__ int g_cnt[16];        // #cj referencing each jr

__device__ __forceinline__ float2 cmul(float2 a, float2 b) {
    return make_float2(fmaf(a.x, b.x, -a.y * b.y), fmaf(a.x, b.y, a.y * b.x));
}

// DIF butterfly, twiddles applied to outputs.
__device__ __forceinline__ void bfly4_dif_t(float2& x0, float2& x1, float2& x2,
                                            float2& x3, float2 w1, float2 w2, float2 w3) {
    float2 t0 = make_float2(x0.x + x2.x, x0.y + x2.y);
    float2 t1 = make_float2(x0.x - x2.x, x0.y - x2.y);
    float2 t2 = make_float2(x1.x + x3.x, x1.y + x3.y);
    float2 t3 = make_float2(x1.x - x3.x, x1.y - x3.y);
    x0 = make_float2(t0.x + t2.x, t0.y + t2.y);
    float2 y1 = make_float2(t1.x + t3.y, t1.y - t3.x);   // t1 - i*t3
    float2 y2 = make_float2(t0.x - t2.x, t0.y - t2.y);
    float2 y3 = make_float2(t1.x - t3.y, t1.y + t3.x);   // t1 + i*t3
    x1 = cmul(y1, w1);
    x2 = cmul(y2, w2);
    x3 = cmul(y3, w3);
}
__device__ __forceinline__ void bfly4_dif(float2& x0, float2& x1, float2& x2,
                                          float2& x3, float2 w1) {
    float2 w2 = cmul(w1, w1);
    bfly4_dif_t(x0, x1, x2, x3, w1, w2, cmul(w2, w1));
}
__device__ __forceinline__ void bfly4_dif_nw(float2& x0, float2& x1,
                                             float2& x2, float2& x3) {
    float2 t0 = make_float2(x0.x + x2.x, x0.y + x2.y);
    float2 t1 = make_float2(x0.x - x2.x, x0.y - x2.y);
    float2 t2 = make_float2(x1.x + x3.x, x1.y + x3.y);
    float2 t3 = make_float2(x1.x - x3.x, x1.y - x3.y);
    x0 = make_float2(t0.x + t2.x, t0.y + t2.y);
    x1 = make_float2(t1.x + t3.y, t1.y - t3.x);
    x2 = make_float2(t0.x - t2.x, t0.y - t2.y);
    x3 = make_float2(t1.x - t3.y, t1.y + t3.x);
}

// DIT butterfly, conjugated twiddles applied to inputs.
__device__ __forceinline__ void bfly4_dit_t(float2& x0, float2& x1, float2& x2,
                                            float2& x3, float2 w1, float2 w2, float2 w3) {
    float2 b1 = cmul(x1, w1);
    float2 b2 = cmul(x2, w2);
    float2 b3 = cmul(x3, w3);
    float2 t0 = make_float2(x0.x + b2.x, x0.y + b2.y);
    float2 t1 = make_float2(x0.x - b2.x, x0.y - b2.y);
    float2 t2 = make_float2(b1.x + b3.x, b1.y + b3.y);
    float2 t3 = make_float2(b1.x - b3.x, b1.y - b3.y);
    x0 = make_float2(t0.x + t2.x, t0.y + t2.y);
    x1 = make_float2(t1.x - t3.y, t1.y + t3.x);          // t1 + i*t3
    x2 = make_float2(t0.x - t2.x, t0.y - t2.y);
    x3 = make_float2(t1.x + t3.y, t1.y - t3.x);          // t1 - i*t3
}
__device__ __forceinline__ void bfly4_dit(float2& x0, float2& x1, float2& x2,
                                          float2& x3, float2 w1c) {
    float2 w2 = cmul(w1c, w1c);
    bfly4_dit_t(x0, x1, x2, x3, w1c, w2, cmul(w2, w1c));
}
__device__ __forceinline__ void bfly4_dit_nw(float2& x0, float2& x1,
                                             float2& x2, float2& x3) {
    float2 t0 = make_float2(x0.x + x2.x, x0.y + x2.y);
    float2 t1 = make_float2(x0.x - x2.x, x0.y - x2.y);
    float2 t2 = make_float2(x1.x + x3.x, x1.y + x3.y);
    float2 t3 = make_float2(x1.x - x3.x, x1.y - x3.y);
    x0 = make_float2(t0.x + t2.x, t0.y + t2.y);
    x1 = make_float2(t1.x - t3.y, t1.y + t3.x);
    x2 = make_float2(t0.x - t2.x, t0.y - t2.y);
    x3 = make_float2(t1.x + t3.y, t1.y - t3.x);
}

// Fused DIF stage pair (S, S+1), one 16-point unit per thread, smem->smem.
template <int S>
__device__ __forceinline__ void fwd_fused_phase(float2* sm, int v) {
    constexpr int l2 = 12 - 2 * S;
    constexpr int L  = 1 << l2;
    constexpr int L4 = L >> 2;
    int block = v >> (l2 - 2);
    int j0 = v & (L4 - 1);
    int base = (block << (l2 + 2)) + j0;
    float2 d[4][4];
#pragma unroll
    for (int m = 0; m < 4; m++)
#pragma unroll
        for (int q = 0; q < 4; q++)
            d[m][q] = sm[P(base + m * L4 + q * L)];
#pragma unroll
    for (int m = 0; m < 4; m++)
        bfly4_dif(d[m][0], d[m][1], d[m][2], d[m][3],
                  g_tw[(j0 + m * L4) << (2 * S)]);
    {
        float2 w1 = g_tw[j0 << (2 * S + 2)];
        float2 w2 = cmul(w1, w1);
        float2 w3 = cmul(w2, w1);
#pragma unroll
        for (int q = 0; q < 4; q++)
            bfly4_dif_t(d[0][q], d[1][q], d[2][q], d[3][q], w1, w2, w3);
    }
#pragma unroll
    for (int m = 0; m < 4; m++)
#pragma unroll
        for (int q = 0; q < 4; q++)
            sm[P(base + m * L4 + q * L)] = d[m][q];
    __syncthreads();
}

// Exact inverse: stage S+1 then S, conjugated twiddles.
template <int S>
__device__ __forceinline__ void inv_fused_phase(float2* sm, int v) {
    constexpr int l2 = 12 - 2 * S;
    constexpr int L  = 1 << l2;
    constexpr int L4 = L >> 2;
    int block = v >> (l2 - 2);
    int j0 = v & (L4 - 1);
    int base = (block << (l2 + 2)) + j0;
    float2 d[4][4];
#pragma unroll
    for (int m = 0; m < 4; m++)
#pragma unroll
        for (int q = 0; q < 4; q++)
            d[m][q] = sm[P(base + m * L4 + q * L)];
    {
        float2 w1 = g_tw[j0 << (2 * S + 2)];
        w1.y = -w1.y;
        float2 w2 = cmul(w1, w1);
        float2 w3 = cmul(w2, w1);
#pragma unroll
        for (int q = 0; q < 4; q++)
            bfly4_dit_t(d[0][q], d[1][q], d[2][q], d[3][q], w1, w2, w3);
    }
#pragma unroll
    for (int m = 0; m < 4; m++) {
        float2 w1 = g_tw[(j0 + m * L4) << (2 * S)];
        w1.y = -w1.y;
        bfly4_dit(d[m][0], d[m][1], d[m][2], d[m][3], w1);
    }
#pragma unroll
    for (int m = 0; m < 4; m++)
#pragma unroll
        for (int q = 0; q < 4; q++)
            sm[P(base + m * L4 + q * L)] = d[m][q];
    __syncthreads();
}

__device__ __forceinline__ int digitrev4(int v) {
    int r = 0;
#pragma unroll
    for (int i = 0; i < 7; i++) { r = (r << 2) | (v & 3); v >>= 2; }
    return r;
}

__global__ void tw_init_kernel() {
    int k = blockIdx.x * blockDim.x + threadIdx.x;
    if (k < N_FFT / 4) {
        double s, c;
        sincospi(-2.0 * (double)k / (double)N_FFT, &s, &c);
        g_tw[k] = make_float2((float)c, (float)s);
    }
}

// Normalize idx (int32/int64 sniff, see R2-R4) + per-jr reference counts.
__global__ void idx_norm_kernel(const int* __restrict__ raw) {
    __shared__ int nz;
    int tid = threadIdx.x;
    if (tid == 0) nz = 0;
    __syncthreads();
    if (tid < 32 && raw[2 * tid + 1] != 0) atomicOr(&nz, 1);
    __syncthreads();
    if (tid < 64) {
        int v = nz ? raw[tid] : raw[2 * tid];
        g_idx[tid] = min(max(v, 0), (tid & 1) ? 25 : 15);
    }
    __syncthreads();
    if (tid == 0) {
        int cnt[16];
        for (int j = 0; j < 16; j++) cnt[j] = 0;
        for (int cj = 0; cj < 32; cj++) cnt[g_idx[2 * cj]]++;
        for (int j = 0; j < 16; j++) g_cnt[j] = cnt[j];
    }
}

// Pre-permute 26 filter spectra (24 psi + phi + phi) into digit-reversed order.
__global__ void filt_prep_kernel(const float* __restrict__ psi,
                                 const float* __restrict__ phi) {
    int p = blockIdx.x * blockDim.x + threadIdx.x;
    int row = p >> 14;
    if (row >= 26) return;
    int q = p & (N_FFT - 1);
    int src = digitrev4(q);
    const float* f = (row < 24) ? (psi + (size_t)row * N_FFT * 2) : phi;
    g_filtrev[p] = make_float2(f[2 * src], f[2 * src + 1]);
}

// Forward: [gmem reflect-read + stages 0,1] -> ph<2> -> ph<4> ->
// [stage 6 + gmem store]. Skips spectra no inverse row references.
__global__ void __launch_bounds__(NT)
fwd_fft_kernel(const float* __restrict__ x) {
    extern __shared__ float2 sm[];
    const int seq = blockIdx.x;
    if (g_cnt[(seq >> 2) & 15] == 0) return;    // dead spectrum
    const float2* xi = (const float2*)(x + (size_t)seq * T_LEN * 2);
    const int tid = threadIdx.x;
    {
        const int v = tid;
        float2 d[4][4];
#pragma unroll
        for (int m = 0; m < 4; m++) {
            int g0 = v + m * 1024;
            d[m][0] = xi[g0];
            d[m][1] = xi[g0 + 4096];
            d[m][2] = xi[8191 - g0];            // reflected half
            d[m][3] = xi[4095 - g0];
        }
#pragma unroll
        for (int m = 0; m < 4; m++)
            bfly4_dif(d[m][0], d[m][1], d[m][2], d[m][3], g_tw[v + m * 1024]);
        {
            float2 w1 = g_tw[v << 2];
            float2 w2 = cmul(w1, w1);
            float2 w3 = cmul(w2, w1);
#pragma unroll
            for (int q = 0; q < 4; q++)
                bfly4_dif_t(d[0][q], d[1][q], d[2][q], d[3][q], w1, w2, w3);
        }
#pragma unroll
        for (int m = 0; m < 4; m++)
#pragma unroll
            for (int q = 0; q < 4; q++)
                sm[P(v + m * 1024 + q * 4096)] = d[m][q];
    }
    __syncthreads();

    fwd_fused_phase<2>(sm, tid);
    fwd_fused_phase<4>(sm, tid);

    float4* out4 = (float4*)(g_xhat + (size_t)seq * N_FFT);
#pragma unroll
    for (int k = 0; k < 4; k++) {
        int base = 4 * (tid + k * NT);
        float2 a0 = sm[P(base)],     a1 = sm[P(base + 1)];
        float2 a2 = sm[P(base + 2)], a3 = sm[P(base + 3)];
        bfly4_dif_nw(a0, a1, a2, a3);
        out4[base >> 1]       = make_float4(a0.x, a0.y, a1.x, a1.y);
        out4[(base >> 1) + 1] = make_float4(a2.x, a2.y, a3.x, a3.y);
    }
}

// Inverse: [gmem gather*filter + stage 6] -> ph<4> -> ph<2> ->
// [stages 1,0 fused with scaled gmem store of the kept half].
__global__ void __launch_bounds__(NT)
inv_fft_kernel(float* __restrict__ out) {
    extern __shared__ float2 sm[];
    const int b  = blockIdx.x;
    const int a  = b & 3;
    const int cj = (b >> 2) & 31;
    const int c  = b >> 7;
    const int jr = g_idx[2 * cj];
    const int f  = g_idx[2 * cj + 1];
    const int src = (c * 16 + jr) * 4 + a;
    const int tid = threadIdx.x;

    const float4* xh4 = (const float4*)(g_xhat + (size_t)src * N_FFT);
    const float4* fr4 = (const float4*)(g_filtrev + (size_t)f * N_FFT);
#pragma unroll
    for (int k = 0; k < 4; k++) {
        int base = 4 * (tid + k * NT);
        float4 xa = xh4[base >> 1], xb = xh4[(base >> 1) + 1];
        float4 fa = fr4[base >> 1], fb = fr4[(base >> 1) + 1];
        float2 a0 = cmul(make_float2(xa.x, xa.y), make_float2(fa.x, fa.y));
        float2 a1 = cmul(make_float2(xa.z, xa.w), make_float2(fa.z, fa.w));
        float2 a2 = cmul(make_float2(xb.x, xb.y), make_float2(fb.x, fb.y));
        float2 a3 = cmul(make_float2(xb.z, xb.w), make_float2(fb.z, fb.w));
        bfly4_dit_nw(a0, a1, a2, a3);
        sm[P(base)] = a0;     sm[P(base + 1)] = a1;
        sm[P(base + 2)] = a2; sm[P(base + 3)] = a3;
    }
    __syncthreads();

    inv_fused_phase<4>(sm, tid);                // stages 5,4
    inv_fused_phase<2>(sm, tid);                // stages 3,2

    // Last phase (stages 1,0) fused with unpad + scaled store: outputs at
    // j0+m*1024+q*4096; only q=0,1 (< 8192) are kept -> straight to gmem.
    {
        const int j0 = tid;                     // L=4096, L4=1024, block=0
        float2 d[4][4];
#pragma unroll
        for (int m = 0; m < 4; m++)
#pragma unroll
            for (int q = 0; q < 4; q++)
                d[m][q] = sm[P(j0 + m * 1024 + q * 4096)];
        // stage 1 inverse: across m for each q
        {
            float2 w1 = g_tw[j0 << 2];
            w1.y = -w1.y;
            float2 w2 = cmul(w1, w1);
            float2 w3 = cmul(w2, w1);
#pragma unroll
            for (int q = 0; q < 4; q++)
                bfly4_dit_t(d[0][q], d[1][q], d[2][q], d[3][q], w1, w2, w3);
        }
        // stage 0 inverse: across q for each m, keep only x0, x1
        float2* o = (float2*)(out + (size_t)b * T_LEN * 2);
        const float scale = 1.0f / (float)N_FFT;
#pragma unroll
        for (int m = 0; m < 4; m++) {
            float2 w1 = g_tw[j0 + m * 1024];
            w1.y = -w1.y;
            float2 w2 = cmul(w1, w1);
            float2 w3 = cmul(w2, w1);
            float2 b1 = cmul(d[m][1], w1);
            float2 b2 = cmul(d[m][2], w2);
            float2 b3 = cmul(d[m][3], w3);
            float2 t0 = make_float2(d[m][0].x + b2.x, d[m][0].y + b2.y);
            float2 t1 = make_float2(d[m][0].x - b2.x, d[m][0].y - b2.y);
            float2 t2 = make_float2(b1.x + b3.x, b1.y + b3.y);
            float2 t3 = make_float2(b1.x - b3.x, b1.y - b3.y);
            float2 x0 = make_float2(t0.x + t2.x, t0.y + t2.y);           // q=0
            float2 x1 = make_float2(t1.x - t3.y, t1.y + t3.x);           // q=1
            o[j0 + m * 1024]        = make_float2(x0.x * scale, x0.y * scale);
            o[j0 + m * 1024 + 4096] = make_float2(x1.x * scale, x1.y * scale);
        }
    }
}

extern "C" void kernel_launch(void* const* d_in, const int* in_sizes, int n_in,
                              void* d_out, int out_size) {
    const float* x   = (const float*)d_in[0];
    const float* psi = (const float*)d_in[1];
    const float* phi = (const float*)d_in[2];
    const int* idxr  = (const int*)d_in[3];
    float* out       = (float*)d_out;

    cudaFuncSetAttribute(fwd_fft_kernel,
                         cudaFuncAttributeMaxDynamicSharedMemorySize, SMEM_BYTES);
    cudaFuncSetAttribute(inv_fft_kernel,
                         cudaFuncAttributeMaxDynamicSharedMemorySize, SMEM_BYTES);

    tw_init_kernel<<<(N_FFT / 4 + 511) / 512, 512>>>();
    idx_norm_kernel<<<1, 64>>>(idxr);
    filt_prep_kernel<<<(26 * N_FFT + 511) / 512, 512>>>(psi, phi);
    fwd_fft_kernel<<<NSEQ, NT, SMEM_BYTES>>>(x);
    inv_fft_kernel<<<1024, NT, SMEM_BYTES>>>(out);
}